// round 1
// baseline (speedup 1.0000x reference)
#include <cuda_runtime.h>
#include <cstdint>

#define N     8192
#define K1    31
#define CAPC  1024     // per-column candidate capacity (expected ~88, max ~135)
#define CAPR  512      // per-row candidate capacity
#define PIVOT 2.3f     // P(z>2.3)=0.0107 -> E[cand]=88 per line

// Scratch (static device allocations are permitted)
__device__ unsigned long long g_colcand[(size_t)N * CAPC]; // 64 MB
__device__ int                g_colcnt[N];
__device__ unsigned long long g_rowth[N];
__device__ unsigned long long g_colth[N];

// Monotone map float -> uint32 (larger float => larger key)
__device__ __forceinline__ unsigned int fkey(float x) {
    unsigned int u = __float_as_uint(x);
    return (u & 0x80000000u) ? ~u : (u | 0x80000000u);
}
// Composite key: value-major, lower index wins ties (stable top_k semantics)
__device__ __forceinline__ unsigned long long ckey(float x, int idx) {
    return ((unsigned long long)fkey(x) << 32) | (unsigned int)(N - 1 - idx);
}

__global__ void zero_kernel() {
    int t = blockIdx.x * blockDim.x + threadIdx.x;
    if (t < N) g_colcnt[t] = 0;
}

// --- generic fallback: find the K1-th largest composite key of a line by
//     K1 iterative bounded-max reductions (exact for ANY input) ---
template <bool ROW>
__device__ unsigned long long fallback_select(const float* __restrict__ A, int line) {
    __shared__ unsigned long long red[256];
    unsigned long long prev = 0xFFFFFFFFFFFFFFFFull;
    for (int it = 0; it < K1; it++) {
        unsigned long long best = 0;
        for (int t = threadIdx.x; t < N; t += 256) {
            float x = ROW ? A[(size_t)line * N + t] : A[(size_t)t * N + line];
            unsigned long long k = ckey(x, t);
            if (k < prev && k > best) best = k;
        }
        red[threadIdx.x] = best;
        __syncthreads();
        for (int s = 128; s > 0; s >>= 1) {
            if (threadIdx.x < s) {
                unsigned long long o = red[threadIdx.x + s];
                if (o > red[threadIdx.x]) red[threadIdx.x] = o;
            }
            __syncthreads();
        }
        prev = red[0];
        __syncthreads();
    }
    return prev;
}

// Kernel A: one block per row. Computes the row threshold AND pushes
// column candidates (value > PIVOT) into global per-column lists.
__global__ __launch_bounds__(256) void rows_kernel(const float* __restrict__ A) {
    const int i = blockIdx.x;
    __shared__ unsigned long long cand[CAPR];
    __shared__ int cnt;
    if (threadIdx.x == 0) cnt = 0;
    __syncthreads();

    const float4* rowp = (const float4*)(A + (size_t)i * N);
    for (int t = threadIdx.x; t < N / 4; t += 256) {
        float4 v = rowp[t];
        float xs[4] = {v.x, v.y, v.z, v.w};
#pragma unroll
        for (int c = 0; c < 4; c++) {
            float x = xs[c];
            if (x > PIVOT) {
                int j = 4 * t + c;
                // row candidate (tiebreak on column index j)
                int s = atomicAdd(&cnt, 1);
                if (s < CAPR) cand[s] = ckey(x, j);
                // column candidate (tiebreak on row index i)
                int cs = atomicAdd(&g_colcnt[j], 1);
                if (cs < CAPC) g_colcand[(size_t)j * CAPC + cs] = ckey(x, i);
            }
        }
    }
    __syncthreads();

    int c = cnt;
    if (c >= K1 && c <= CAPR) {
        // rank-by-counting among candidates: exactly one key has rank K1-1
        for (int t = threadIdx.x; t < c; t += 256) {
            unsigned long long kt = cand[t];
            int r = 0;
            for (int m = 0; m < c; m++) r += (cand[m] > kt);
            if (r == K1 - 1) g_rowth[i] = kt;
        }
    } else {
        unsigned long long th = fallback_select<true>(A, i);
        if (threadIdx.x == 0) g_rowth[i] = th;
    }
}

// Kernel B: one block per column. Threshold from the candidate list.
__global__ __launch_bounds__(256) void cols_kernel(const float* __restrict__ A) {
    const int j = blockIdx.x;
    const int c = g_colcnt[j];
    __shared__ unsigned long long cand[CAPC]; // 8 KB
    if (c >= K1 && c <= CAPC) {
        for (int t = threadIdx.x; t < c; t += 256)
            cand[t] = g_colcand[(size_t)j * CAPC + t];
        __syncthreads();
        for (int t = threadIdx.x; t < c; t += 256) {
            unsigned long long kt = cand[t];
            int r = 0;
            for (int m = 0; m < c; m++) r += (cand[m] > kt);
            if (r == K1 - 1) g_colth[j] = kt;
        }
    } else {
        unsigned long long th = fallback_select<false>(A, j);
        if (threadIdx.x == 0) g_colth[j] = th;
    }
}

// Kernel C: elementwise mask. out = a if (row-key >= rowth && col-key >= colth && i != j)
__global__ __launch_bounds__(256) void mask_kernel(const float* __restrict__ A,
                                                   float* __restrict__ out) {
    const size_t gid = (size_t)blockIdx.x * 256 + threadIdx.x; // over N*N/4
    const int i  = (int)(gid >> 11);       // N/4 = 2048 float4 per row
    const int t4 = (int)(gid & 2047);
    float4 v = ((const float4*)A)[(size_t)i * 2048 + t4];
    const unsigned long long rth = g_rowth[i];
    float xs[4] = {v.x, v.y, v.z, v.w};
    float os[4];
#pragma unroll
    for (int c = 0; c < 4; c++) {
        int j = 4 * t4 + c;
        float x = xs[c];
        bool ok = (i != j) &&
                  (ckey(x, j) >= rth) &&
                  (ckey(x, i) >= __ldg(&g_colth[j]));
        os[c] = ok ? x : 0.0f;
    }
    float4 o = {os[0], os[1], os[2], os[3]};
    ((float4*)out)[(size_t)i * 2048 + t4] = o;
}

extern "C" void kernel_launch(void* const* d_in, const int* in_sizes, int n_in,
                              void* d_out, int out_size) {
    const float* A = (const float*)d_in[0];
    float* out = (float*)d_out;
    zero_kernel<<<(N + 255) / 256, 256>>>();
    rows_kernel<<<N, 256>>>(A);
    cols_kernel<<<N, 256>>>(A);
    mask_kernel<<<(size_t)N * (N / 4) / 256, 256>>>(A, out);
}

// round 2
// speedup vs baseline: 1.4146x; 1.4146x over previous
#include <cuda_runtime.h>
#include <cstdint>

#define N     8192
#define K1    31
#define CAPC  1024     // per-column candidate capacity (expected ~88, max ~135)
#define CAPR  512      // per-row candidate capacity
#define PIVOT 2.3f     // P(z>2.3)=0.0107 -> E[cand]=88 per line

__device__ unsigned long long g_colcand[(size_t)N * CAPC]; // 64 MB scratch
__device__ int                g_colcnt[N];
__device__ unsigned long long g_rowth[N];
__device__ unsigned long long g_colth[N];

// Monotone map float -> uint32 (larger float => larger key)
__device__ __forceinline__ unsigned int fkey(float x) {
    unsigned int u = __float_as_uint(x);
    return (u & 0x80000000u) ? ~u : (u | 0x80000000u);
}
__device__ __forceinline__ float inv_fkey(unsigned int k) {
    unsigned int u = (k & 0x80000000u) ? (k ^ 0x80000000u) : ~k;
    return __uint_as_float(u);
}
// Composite key: value-major, lower index wins ties (stable top_k semantics)
__device__ __forceinline__ unsigned long long ckey(float x, int idx) {
    return ((unsigned long long)fkey(x) << 32) | (unsigned int)(N - 1 - idx);
}

__global__ void zero_kernel() {
    int t = blockIdx.x * blockDim.x + threadIdx.x;
    if (t < N) g_colcnt[t] = 0;
}

// --- generic fallback: find the K1-th largest composite key of a line by
//     K1 iterative bounded-max reductions (exact for ANY input) ---
template <bool ROW>
__device__ unsigned long long fallback_select(const float* __restrict__ A, int line) {
    __shared__ unsigned long long red[256];
    unsigned long long prev = 0xFFFFFFFFFFFFFFFFull;
    for (int it = 0; it < K1; it++) {
        unsigned long long best = 0;
        for (int t = threadIdx.x; t < N; t += 256) {
            float x = ROW ? A[(size_t)line * N + t] : A[(size_t)t * N + line];
            unsigned long long k = ckey(x, t);
            if (k < prev && k > best) best = k;
        }
        red[threadIdx.x] = best;
        __syncthreads();
        for (int s = 128; s > 0; s >>= 1) {
            if (threadIdx.x < s) {
                unsigned long long o = red[threadIdx.x + s];
                if (o > red[threadIdx.x]) red[threadIdx.x] = o;
            }
            __syncthreads();
        }
        prev = red[0];
        __syncthreads();
    }
    return prev;
}

// Kernel A (fused): one block per row.
//  - streams row i of A (256MB total read)
//  - writes zeros to row i of out (256MB total write)  [scatter fills nonzeros later]
//  - collects row candidates -> row threshold
//  - pushes column candidates into global per-column lists
__global__ __launch_bounds__(256) void rows_kernel(const float* __restrict__ A,
                                                   float* __restrict__ out) {
    const int i = blockIdx.x;
    __shared__ unsigned long long cand[CAPR];
    __shared__ int cnt;
    if (threadIdx.x == 0) cnt = 0;
    __syncthreads();

    const float4* rowp = (const float4*)(A + (size_t)i * N);
    float4* outp = (float4*)(out + (size_t)i * N);
    const float4 zz = {0.0f, 0.0f, 0.0f, 0.0f};
    for (int t = threadIdx.x; t < N / 4; t += 256) {
        float4 v = rowp[t];
        outp[t] = zz;
        float xs[4] = {v.x, v.y, v.z, v.w};
#pragma unroll
        for (int c = 0; c < 4; c++) {
            float x = xs[c];
            if (x > PIVOT) {
                int j = 4 * t + c;
                int s = atomicAdd(&cnt, 1);
                if (s < CAPR) cand[s] = ckey(x, j);            // row candidate
                int cs = atomicAdd(&g_colcnt[j], 1);
                if (cs < CAPC) g_colcand[(size_t)j * CAPC + cs] = ckey(x, i); // col candidate
            }
        }
    }
    __syncthreads();

    int c = cnt;
    if (c >= K1 && c <= CAPR) {
        for (int t = threadIdx.x; t < c; t += 256) {
            unsigned long long kt = cand[t];
            int r = 0;
            for (int m = 0; m < c; m++) r += (cand[m] > kt);
            if (r == K1 - 1) g_rowth[i] = kt;
        }
    } else {
        unsigned long long th = fallback_select<true>(A, i);
        if (threadIdx.x == 0) g_rowth[i] = th;
    }
}

// Kernel B: one block per column. Threshold from the candidate list.
__global__ __launch_bounds__(256) void cols_kernel(const float* __restrict__ A) {
    const int j = blockIdx.x;
    const int c = g_colcnt[j];
    __shared__ unsigned long long cand[CAPC];
    if (c >= K1 && c <= CAPC) {
        for (int t = threadIdx.x; t < c; t += 256)
            cand[t] = g_colcand[(size_t)j * CAPC + t];
        __syncthreads();
        for (int t = threadIdx.x; t < c; t += 256) {
            unsigned long long kt = cand[t];
            int r = 0;
            for (int m = 0; m < c; m++) r += (cand[m] > kt);
            if (r == K1 - 1) g_colth[j] = kt;
        }
    } else {
        unsigned long long th = fallback_select<false>(A, j);
        if (threadIdx.x == 0) g_colth[j] = th;
    }
}

// Kernel C: scatter. Every entry passing BOTH thresholds has value > PIVOT
// (both thresholds are keys of candidates > PIVOT), so it appears in the
// column candidate lists. Iterate those and write survivors.
__global__ __launch_bounds__(128) void scatter_kernel(float* __restrict__ out) {
    const int j = blockIdx.x;
    int c = g_colcnt[j];
    if (c > CAPC) c = CAPC;
    const unsigned long long cth = g_colth[j];
    for (int s = threadIdx.x; s < c; s += 128) {
        unsigned long long k = g_colcand[(size_t)j * CAPC + s];
        if (k < cth) continue;                       // fails column top-k
        int i = N - 1 - (int)(unsigned int)(k & 0xFFFFFFFFu);
        if (i == j) continue;                        // no self-loop
        float x = inv_fkey((unsigned int)(k >> 32));
        if (ckey(x, j) >= g_rowth[i])                // passes row top-k
            out[(size_t)i * N + j] = x;
    }
}

extern "C" void kernel_launch(void* const* d_in, const int* in_sizes, int n_in,
                              void* d_out, int out_size) {
    const float* A = (const float*)d_in[0];
    float* out = (float*)d_out;
    zero_kernel<<<(N + 255) / 256, 256>>>();
    rows_kernel<<<N, 256>>>(A, out);
    cols_kernel<<<N, 256>>>(A);
    scatter_kernel<<<N, 128>>>(out);
}